// round 6
// baseline (speedup 1.0000x reference)
#include <cuda_runtime.h>

#define NTOT  65536
#define BGRAPH 64
#define NPG   1024
#define KC    128
#define DD    128
#define EDGES 1048576

// ---------------- scratch (device globals: allocation-free) ----------------
__device__ int   g_is64;
__device__ int   g_src[EDGES];
__device__ int   g_dst[EDGES];
__device__ int   g_deg[NTOT];
__device__ int   g_cur[NTOT];
__device__ int   g_off[NTOT + 1];
__device__ int   g_adj[EDGES];
__device__ float g_neigh[(size_t)NTOT * 128];   // 32 MB

// ---------------- packed f32x2 helpers (Blackwell FFMA2 path) --------------
__device__ __forceinline__ unsigned long long pack2(float lo, float hi) {
    unsigned long long r;
    asm("mov.b64 %0, {%1, %2};" : "=l"(r) : "f"(lo), "f"(hi));
    return r;
}
__device__ __forceinline__ void ffma2(unsigned long long& d,
                                      unsigned long long a,
                                      unsigned long long b) {
    asm("fma.rn.f32x2 %0, %1, %2, %0;" : "+l"(d) : "l"(a), "l"(b));
}
__device__ __forceinline__ float2 unpack2(unsigned long long v) {
    float2 f;
    asm("mov.b64 {%0, %1}, %2;" : "=f"(f.x), "=f"(f.y) : "l"(v));
    return f;
}

// ---------------- edge dtype detection + normalization ----------------
// If edges are int64 little-endian, the high 32-bit word of each element is 0
// (node ids < 2^31). If they are int32, the odd-index words are random node
// ids. Check 8 odd words of each buffer: all-zero => int64.
__global__ void k_detect(const int* __restrict__ es, const int* __restrict__ ed) {
    int allzero = 1;
#pragma unroll
    for (int i = 1; i <= 15; i += 2) {
        allzero &= (es[i] == 0);
        allzero &= (ed[i] == 0);
    }
    g_is64 = allzero;
}

__global__ void k_convert(const void* __restrict__ src, const void* __restrict__ dst) {
    int e = blockIdx.x * blockDim.x + threadIdx.x;
    if (e >= EDGES) return;
    if (g_is64) {
        g_src[e] = (int)((const long long*)src)[e];
        g_dst[e] = (int)((const long long*)dst)[e];
    } else {
        g_src[e] = ((const int*)src)[e];
        g_dst[e] = ((const int*)dst)[e];
    }
}

// ---------------- CSR build ----------------
__global__ void k_init() {
    int i = blockIdx.x * blockDim.x + threadIdx.x;
    if (i < NTOT) { g_deg[i] = 0; g_cur[i] = 0; }
}

__global__ void k_count() {
    int e = blockIdx.x * blockDim.x + threadIdx.x;
    if (e < EDGES) {
        int d = g_dst[e];
        if (d >= 0 && d < NTOT) atomicAdd(&g_deg[d], 1);
    }
}

// single-block exclusive scan over 65536 ints (1024 threads x 64 each)
__global__ void k_scan() {
    __shared__ int sums[1024];
    int t = threadIdx.x;
    int base = t * 64;
    int s = 0;
#pragma unroll 4
    for (int i = 0; i < 64; i++) s += g_deg[base + i];
    sums[t] = s;
    __syncthreads();
    for (int off = 1; off < 1024; off <<= 1) {
        int v = (t >= off) ? sums[t - off] : 0;
        __syncthreads();
        sums[t] += v;
        __syncthreads();
    }
    int run = (t == 0) ? 0 : sums[t - 1];
    for (int i = 0; i < 64; i++) {
        g_off[base + i] = run;
        run += g_deg[base + i];
    }
    if (t == 1023) g_off[NTOT] = run;
}

__global__ void k_fill() {
    int e = blockIdx.x * blockDim.x + threadIdx.x;
    if (e < EDGES) {
        int d = g_dst[e];
        int s = g_src[e];
        if (d >= 0 && d < NTOT && s >= 0 && s < NTOT) {
            int pos = atomicAdd(&g_cur[d], 1);
            g_adj[g_off[d] + pos] = s;
        }
    }
}

// ---------------- aggregation: one warp per node, no float atomics ---------
__global__ void k_agg(const float* __restrict__ h) {
    int gw = (blockIdx.x * blockDim.x + threadIdx.x) >> 5;
    if (gw >= NTOT) return;
    int lane = threadIdx.x & 31;
    int s = g_off[gw], e = g_off[gw + 1];
    float4 acc = make_float4(0.f, 0.f, 0.f, 0.f);
    int j = s;
    for (; j + 4 <= e; j += 4) {
        int i0 = g_adj[j], i1 = g_adj[j + 1], i2 = g_adj[j + 2], i3 = g_adj[j + 3];
        float4 v0 = __ldg((const float4*)(h + (size_t)i0 * 128) + lane);
        float4 v1 = __ldg((const float4*)(h + (size_t)i1 * 128) + lane);
        float4 v2 = __ldg((const float4*)(h + (size_t)i2 * 128) + lane);
        float4 v3 = __ldg((const float4*)(h + (size_t)i3 * 128) + lane);
        acc.x += (v0.x + v1.x) + (v2.x + v3.x);
        acc.y += (v0.y + v1.y) + (v2.y + v3.y);
        acc.z += (v0.z + v1.z) + (v2.z + v3.z);
        acc.w += (v0.w + v1.w) + (v2.w + v3.w);
    }
    for (; j < e; j++) {
        int i0 = g_adj[j];
        float4 v0 = __ldg((const float4*)(h + (size_t)i0 * 128) + lane);
        acc.x += v0.x; acc.y += v0.y; acc.z += v0.z; acc.w += v0.w;
    }
    float inv = 1.0f / fmaxf((float)(e - s), 1.0f);
    float4 o = make_float4(acc.x * inv, acc.y * inv, acc.z * inv, acc.w * inv);
    *(float4*)(g_neigh + (size_t)gw * 128 + lane * 4) = o;
}

// ---------------- fused: GEMM1 (K=256) + bias + relu + softmax + GEMM2 -----
// Tile: 64 nodes x 128 cols per block, 256 threads.
// smem: sA [64][256] (h | neigh)  = 64KB
//       sW [256][128] (Ws ; Wn)   = 128KB
//       sB [128]                  = 512B
// phase2 aliases: sAssign -> sA region, sFea -> sW region.
#define SMEM_FLOATS (64 * 256 + 256 * 128 + 128)
#define SMEM_BYTES  (SMEM_FLOATS * 4)

extern __shared__ float smem[];

__global__ void __launch_bounds__(256, 1)
k_fused(const float* __restrict__ h,
        const float* __restrict__ fea,
        const float* __restrict__ Ws,
        const float* __restrict__ Wn,
        const float* __restrict__ bias,
        float* __restrict__ out) {
    float* sA = smem;                    // 64*256
    float* sW = smem + 64 * 256;         // 256*128
    float* sB = sW + 256 * 128;          // 128

    const int tid = threadIdx.x;
    const int node0 = blockIdx.x * 64;

    // ---- load A tile (h cols 0..127, neigh cols 128..255) + W + bias ----
    for (int i = tid; i < 64 * 32; i += 256) {
        int r = i >> 5, c = (i & 31) << 2;
        *(float4*)(sA + r * 256 + c) =
            *(const float4*)(h + (size_t)(node0 + r) * 128 + c);
        *(float4*)(sA + r * 256 + 128 + c) =
            *(const float4*)(g_neigh + (size_t)(node0 + r) * 128 + c);
    }
    for (int i = tid; i < 128 * 32; i += 256) {
        int r = i >> 5, c = (i & 31) << 2;
        *(float4*)(sW + r * 128 + c)         = *(const float4*)(Ws + r * 128 + c);
        *(float4*)(sW + (128 + r) * 128 + c) = *(const float4*)(Wn + r * 128 + c);
    }
    if (tid < 128) sB[tid] = bias[tid];
    __syncthreads();

    const int lane = tid & 31, wrp = tid >> 5;
    const int n0 = wrp * 8;        // 8 nodes per thread
    const int c0 = lane * 4;       // 4 cols per thread (as 2 f32x2 pairs)

    unsigned long long acc2[8][2];
#pragma unroll
    for (int i = 0; i < 8; i++) { acc2[i][0] = 0ULL; acc2[i][1] = 0ULL; }

    // ---- GEMM1: logits = [h|neigh] @ [Ws;Wn] ----
    for (int kk = 0; kk < 256; kk += 4) {
        float w_[4][4];
#pragma unroll
        for (int q = 0; q < 4; q++) {
            float4 t = *(const float4*)(sW + (kk + q) * 128 + c0);
            w_[q][0] = t.x; w_[q][1] = t.y; w_[q][2] = t.z; w_[q][3] = t.w;
        }
        float a_[8][4];
#pragma unroll
        for (int i = 0; i < 8; i++) {
            float4 t = *(const float4*)(sA + (n0 + i) * 256 + kk);
            a_[i][0] = t.x; a_[i][1] = t.y; a_[i][2] = t.z; a_[i][3] = t.w;
        }
#pragma unroll
        for (int q = 0; q < 4; q++) {
            unsigned long long w01 = pack2(w_[q][0], w_[q][1]);
            unsigned long long w23 = pack2(w_[q][2], w_[q][3]);
#pragma unroll
            for (int i = 0; i < 8; i++) {
                unsigned long long aa = pack2(a_[i][q], a_[i][q]);
                ffma2(acc2[i][0], aa, w01);
                ffma2(acc2[i][1], aa, w23);
            }
        }
    }

    // ---- bias + relu + row softmax (row lives in one warp: 4 cols/lane) ----
    float4 b4 = *(const float4*)(sB + c0);
    float probs[8][4];
#pragma unroll
    for (int i = 0; i < 8; i++) {
        float2 v01 = unpack2(acc2[i][0]);
        float2 v23 = unpack2(acc2[i][1]);
        float x0 = fmaxf(v01.x + b4.x, 0.f);
        float x1 = fmaxf(v01.y + b4.y, 0.f);
        float x2 = fmaxf(v23.x + b4.z, 0.f);
        float x3 = fmaxf(v23.y + b4.w, 0.f);
        float m = fmaxf(fmaxf(x0, x1), fmaxf(x2, x3));
#pragma unroll
        for (int o = 16; o > 0; o >>= 1)
            m = fmaxf(m, __shfl_xor_sync(0xffffffffu, m, o));
        x0 = __expf(x0 - m); x1 = __expf(x1 - m);
        x2 = __expf(x2 - m); x3 = __expf(x3 - m);
        float ssum = (x0 + x1) + (x2 + x3);
#pragma unroll
        for (int o = 16; o > 0; o >>= 1)
            ssum += __shfl_xor_sync(0xffffffffu, ssum, o);
        float inv = 1.0f / ssum;
        probs[i][0] = x0 * inv; probs[i][1] = x1 * inv;
        probs[i][2] = x2 * inv; probs[i][3] = x3 * inv;
    }

    __syncthreads();   // everyone done reading sA/sW before aliasing

    float* sAssign = sA;   // [64][128]
    float* sFea    = sW;   // [128][128]
#pragma unroll
    for (int i = 0; i < 8; i++) {
        *(float4*)(sAssign + (n0 + i) * 128 + c0) =
            make_float4(probs[i][0], probs[i][1], probs[i][2], probs[i][3]);
    }
    {   // load per-graph fea slice (graph = node0 / 1024)
        const float* feaG = fea + (size_t)(node0 >> 10) * KC * DD;
        for (int i = tid; i < 128 * 32; i += 256) {
            int r = i >> 5, c = (i & 31) << 2;
            *(float4*)(sFea + r * 128 + c) = *(const float4*)(feaG + r * 128 + c);
        }
    }
    __syncthreads();

    // ---- GEMM2: out = assign @ fea_g (K=128) ----
    unsigned long long o2[8][2];
#pragma unroll
    for (int i = 0; i < 8; i++) { o2[i][0] = 0ULL; o2[i][1] = 0ULL; }

    for (int kk = 0; kk < 128; kk += 4) {
        float w_[4][4];
#pragma unroll
        for (int q = 0; q < 4; q++) {
            float4 t = *(const float4*)(sFea + (kk + q) * 128 + c0);
            w_[q][0] = t.x; w_[q][1] = t.y; w_[q][2] = t.z; w_[q][3] = t.w;
        }
        float a_[8][4];
#pragma unroll
        for (int i = 0; i < 8; i++) {
            float4 t = *(const float4*)(sAssign + (n0 + i) * 128 + kk);
            a_[i][0] = t.x; a_[i][1] = t.y; a_[i][2] = t.z; a_[i][3] = t.w;
        }
#pragma unroll
        for (int q = 0; q < 4; q++) {
            unsigned long long w01 = pack2(w_[q][0], w_[q][1]);
            unsigned long long w23 = pack2(w_[q][2], w_[q][3]);
#pragma unroll
            for (int i = 0; i < 8; i++) {
                unsigned long long aa = pack2(a_[i][q], a_[i][q]);
                ffma2(o2[i][0], aa, w01);
                ffma2(o2[i][1], aa, w23);
            }
        }
    }

#pragma unroll
    for (int i = 0; i < 8; i++) {
        float2 v01 = unpack2(o2[i][0]);
        float2 v23 = unpack2(o2[i][1]);
        *(float4*)(out + (size_t)(node0 + n0 + i) * 128 + c0) =
            make_float4(v01.x, v01.y, v23.x, v23.y);
    }
}

// ---------------- launch ----------------
extern "C" void kernel_launch(void* const* d_in, const int* in_sizes, int n_in,
                              void* d_out, int out_size) {
    (void)in_sizes; (void)n_in; (void)out_size;
    const float* h    = (const float*)d_in[0];
    const float* fea  = (const float*)d_in[1];
    const float* Ws   = (const float*)d_in[2];
    const float* Wn   = (const float*)d_in[3];
    const float* bias = (const float*)d_in[4];
    const void*  esrc = d_in[5];
    const void*  edst = d_in[6];
    float* out = (float*)d_out;

    cudaFuncSetAttribute(k_fused, cudaFuncAttributeMaxDynamicSharedMemorySize,
                         SMEM_BYTES);

    k_detect <<<1, 1>>>((const int*)esrc, (const int*)edst);
    k_convert<<<(EDGES + 255) / 256, 256>>>(esrc, edst);
    k_init   <<<(NTOT + 255) / 256, 256>>>();
    k_count  <<<(EDGES + 255) / 256, 256>>>();
    k_scan   <<<1, 1024>>>();
    k_fill   <<<(EDGES + 255) / 256, 256>>>();
    k_agg    <<<(NTOT * 32) / 256, 256>>>(h);
    k_fused  <<<NTOT / 64, 256, SMEM_BYTES>>>(h, fea, Ws, Wn, bias, out);
}

// round 8
// speedup vs baseline: 1.0071x; 1.0071x over previous
#include <cuda_runtime.h>

#define NTOT  65536
#define BGRAPH 64
#define NPG   1024
#define KC    128
#define DD    128
#define EDGES 1048576

// ---------------- scratch (device globals: allocation-free) ----------------
__device__ int   g_is64;
__device__ int   g_deg[NTOT];
__device__ int   g_cur[NTOT];
__device__ int   g_off[NTOT + 1];
__device__ int   g_adj[EDGES];
__device__ float g_neigh[(size_t)NTOT * 128];   // 32 MB

// ---------------- packed f32x2 helpers (Blackwell FFMA2 path) --------------
__device__ __forceinline__ unsigned long long pack2(float lo, float hi) {
    unsigned long long r;
    asm("mov.b64 %0, {%1, %2};" : "=l"(r) : "f"(lo), "f"(hi));
    return r;
}
__device__ __forceinline__ void ffma2(unsigned long long& d,
                                      unsigned long long a,
                                      unsigned long long b) {
    asm("fma.rn.f32x2 %0, %1, %2, %0;" : "+l"(d) : "l"(a), "l"(b));
}
__device__ __forceinline__ float2 unpack2(unsigned long long v) {
    float2 f;
    asm("mov.b64 {%0, %1}, %2;" : "=f"(f.x), "=f"(f.y) : "l"(v));
    return f;
}

// ---------------- edge index fetch (dtype-agnostic) ----------------
// If edges are int64 little-endian (ids < 2^31), every odd 32-bit word is 0.
// For int32 data those words are random node ids. Detection runs once in
// k_init; count/fill branch uniformly on g_is64 and read in place.
__device__ __forceinline__ int edge_id(const void* buf, int e, int is64) {
    return is64 ? (int)((const long long*)buf)[e] : ((const int*)buf)[e];
}

// ---------------- init (zero counters) + dtype detect ----------------
__global__ void k_init(const int* __restrict__ es, const int* __restrict__ ed) {
    int i = blockIdx.x * blockDim.x + threadIdx.x;
    if (i < NTOT) { g_deg[i] = 0; g_cur[i] = 0; }
    if (i == 0) {
        int allzero = 1;
#pragma unroll
        for (int k = 1; k <= 15; k += 2) {
            allzero &= (es[k] == 0);
            allzero &= (ed[k] == 0);
        }
        g_is64 = allzero;
    }
}

// ---------------- CSR build ----------------
__global__ void k_count(const void* __restrict__ dst) {
    int e = blockIdx.x * blockDim.x + threadIdx.x;
    if (e < EDGES) {
        int d = edge_id(dst, e, g_is64);
        if (d >= 0 && d < NTOT) atomicAdd(&g_deg[d], 1);
    }
}

// single-block exclusive scan over 65536 ints (1024 threads x 64 each)
__global__ void k_scan() {
    __shared__ int sums[1024];
    int t = threadIdx.x;
    int base = t * 64;
    int s = 0;
#pragma unroll 4
    for (int i = 0; i < 64; i++) s += g_deg[base + i];
    sums[t] = s;
    __syncthreads();
    for (int off = 1; off < 1024; off <<= 1) {
        int v = (t >= off) ? sums[t - off] : 0;
        __syncthreads();
        sums[t] += v;
        __syncthreads();
    }
    int run = (t == 0) ? 0 : sums[t - 1];
    for (int i = 0; i < 64; i++) {
        g_off[base + i] = run;
        run += g_deg[base + i];
    }
    if (t == 1023) g_off[NTOT] = run;
}

__global__ void k_fill(const void* __restrict__ src, const void* __restrict__ dst) {
    int e = blockIdx.x * blockDim.x + threadIdx.x;
    if (e < EDGES) {
        int is64 = g_is64;
        int d = edge_id(dst, e, is64);
        int s = edge_id(src, e, is64);
        if (d >= 0 && d < NTOT && s >= 0 && s < NTOT) {
            int pos = atomicAdd(&g_cur[d], 1);
            g_adj[g_off[d] + pos] = s;
        }
    }
}

// ---------------- aggregation: one warp per node, no float atomics ---------
__global__ void k_agg(const float* __restrict__ h) {
    int gw = (blockIdx.x * blockDim.x + threadIdx.x) >> 5;
    if (gw >= NTOT) return;
    int lane = threadIdx.x & 31;
    int s = g_off[gw], e = g_off[gw + 1];
    float4 acc = make_float4(0.f, 0.f, 0.f, 0.f);
    int j = s;
    // 8-deep unroll: 8 outstanding LDG.128 per lane to cover L2/DRAM latency
    for (; j + 8 <= e; j += 8) {
        int idx[8];
#pragma unroll
        for (int q = 0; q < 8; q++) idx[q] = g_adj[j + q];
        float4 v[8];
#pragma unroll
        for (int q = 0; q < 8; q++)
            v[q] = __ldg((const float4*)(h + (size_t)idx[q] * 128) + lane);
#pragma unroll
        for (int q = 0; q < 8; q++) {
            acc.x += v[q].x; acc.y += v[q].y;
            acc.z += v[q].z; acc.w += v[q].w;
        }
    }
    for (; j < e; j++) {
        int i0 = g_adj[j];
        float4 v0 = __ldg((const float4*)(h + (size_t)i0 * 128) + lane);
        acc.x += v0.x; acc.y += v0.y; acc.z += v0.z; acc.w += v0.w;
    }
    float inv = 1.0f / fmaxf((float)(e - s), 1.0f);
    float4 o = make_float4(acc.x * inv, acc.y * inv, acc.z * inv, acc.w * inv);
    *(float4*)(g_neigh + (size_t)gw * 128 + lane * 4) = o;
}

// ---------------- fused: GEMM1 (K=256) + bias + relu + softmax + GEMM2 -----
// Tile: 64 nodes x 128 cols per block, 256 threads.
// smem: sA [64][256] (h | neigh)  = 64KB
//       sW [256][128] (Ws ; Wn)   = 128KB
//       sB [128]                  = 512B
// phase2 aliases: sAssign -> sA region, sFea -> sW region.
#define SMEM_FLOATS (64 * 256 + 256 * 128 + 128)
#define SMEM_BYTES  (SMEM_FLOATS * 4)

extern __shared__ float smem[];

__global__ void __launch_bounds__(256, 1)
k_fused(const float* __restrict__ h,
        const float* __restrict__ fea,
        const float* __restrict__ Ws,
        const float* __restrict__ Wn,
        const float* __restrict__ bias,
        float* __restrict__ out) {
    float* sA = smem;                    // 64*256
    float* sW = smem + 64 * 256;         // 256*128
    float* sB = sW + 256 * 128;          // 128

    const int tid = threadIdx.x;
    const int node0 = blockIdx.x * 64;

    // ---- load A tile (h cols 0..127, neigh cols 128..255) + W + bias ----
    for (int i = tid; i < 64 * 32; i += 256) {
        int r = i >> 5, c = (i & 31) << 2;
        *(float4*)(sA + r * 256 + c) =
            *(const float4*)(h + (size_t)(node0 + r) * 128 + c);
        *(float4*)(sA + r * 256 + 128 + c) =
            *(const float4*)(g_neigh + (size_t)(node0 + r) * 128 + c);
    }
    for (int i = tid; i < 128 * 32; i += 256) {
        int r = i >> 5, c = (i & 31) << 2;
        *(float4*)(sW + r * 128 + c)         = *(const float4*)(Ws + r * 128 + c);
        *(float4*)(sW + (128 + r) * 128 + c) = *(const float4*)(Wn + r * 128 + c);
    }
    if (tid < 128) sB[tid] = bias[tid];
    __syncthreads();

    const int lane = tid & 31, wrp = tid >> 5;
    const int n0 = wrp * 8;        // 8 nodes per thread
    const int c0 = lane * 4;       // 4 cols per thread (as 2 f32x2 pairs)

    unsigned long long acc2[8][2];
#pragma unroll
    for (int i = 0; i < 8; i++) { acc2[i][0] = 0ULL; acc2[i][1] = 0ULL; }

    // ---- GEMM1: logits = [h|neigh] @ [Ws;Wn] ----
    for (int kk = 0; kk < 256; kk += 4) {
        float w_[4][4];
#pragma unroll
        for (int q = 0; q < 4; q++) {
            float4 t = *(const float4*)(sW + (kk + q) * 128 + c0);
            w_[q][0] = t.x; w_[q][1] = t.y; w_[q][2] = t.z; w_[q][3] = t.w;
        }
        float a_[8][4];
#pragma unroll
        for (int i = 0; i < 8; i++) {
            float4 t = *(const float4*)(sA + (n0 + i) * 256 + kk);
            a_[i][0] = t.x; a_[i][1] = t.y; a_[i][2] = t.z; a_[i][3] = t.w;
        }
#pragma unroll
        for (int q = 0; q < 4; q++) {
            unsigned long long w01 = pack2(w_[q][0], w_[q][1]);
            unsigned long long w23 = pack2(w_[q][2], w_[q][3]);
#pragma unroll
            for (int i = 0; i < 8; i++) {
                unsigned long long aa = pack2(a_[i][q], a_[i][q]);
                ffma2(acc2[i][0], aa, w01);
                ffma2(acc2[i][1], aa, w23);
            }
        }
    }

    // ---- bias + relu + row softmax (row lives in one warp: 4 cols/lane) ----
    float4 b4 = *(const float4*)(sB + c0);
    float probs[8][4];
#pragma unroll
    for (int i = 0; i < 8; i++) {
        float2 v01 = unpack2(acc2[i][0]);
        float2 v23 = unpack2(acc2[i][1]);
        float x0 = fmaxf(v01.x + b4.x, 0.f);
        float x1 = fmaxf(v01.y + b4.y, 0.f);
        float x2 = fmaxf(v23.x + b4.z, 0.f);
        float x3 = fmaxf(v23.y + b4.w, 0.f);
        float m = fmaxf(fmaxf(x0, x1), fmaxf(x2, x3));
#pragma unroll
        for (int o = 16; o > 0; o >>= 1)
            m = fmaxf(m, __shfl_xor_sync(0xffffffffu, m, o));
        x0 = __expf(x0 - m); x1 = __expf(x1 - m);
        x2 = __expf(x2 - m); x3 = __expf(x3 - m);
        float ssum = (x0 + x1) + (x2 + x3);
#pragma unroll
        for (int o = 16; o > 0; o >>= 1)
            ssum += __shfl_xor_sync(0xffffffffu, ssum, o);
        float inv = 1.0f / ssum;
        probs[i][0] = x0 * inv; probs[i][1] = x1 * inv;
        probs[i][2] = x2 * inv; probs[i][3] = x3 * inv;
    }

    __syncthreads();   // everyone done reading sA/sW before aliasing

    float* sAssign = sA;   // [64][128]
    float* sFea    = sW;   // [128][128]
#pragma unroll
    for (int i = 0; i < 8; i++) {
        *(float4*)(sAssign + (n0 + i) * 128 + c0) =
            make_float4(probs[i][0], probs[i][1], probs[i][2], probs[i][3]);
    }
    {   // load per-graph fea slice (graph = node0 / 1024)
        const float* feaG = fea + (size_t)(node0 >> 10) * KC * DD;
        for (int i = tid; i < 128 * 32; i += 256) {
            int r = i >> 5, c = (i & 31) << 2;
            *(float4*)(sFea + r * 128 + c) = *(const float4*)(feaG + r * 128 + c);
        }
    }
    __syncthreads();

    // ---- GEMM2: out = assign @ fea_g (K=128) ----
    unsigned long long o2[8][2];
#pragma unroll
    for (int i = 0; i < 8; i++) { o2[i][0] = 0ULL; o2[i][1] = 0ULL; }

    for (int kk = 0; kk < 128; kk += 4) {
        float w_[4][4];
#pragma unroll
        for (int q = 0; q < 4; q++) {
            float4 t = *(const float4*)(sFea + (kk + q) * 128 + c0);
            w_[q][0] = t.x; w_[q][1] = t.y; w_[q][2] = t.z; w_[q][3] = t.w;
        }
        float a_[8][4];
#pragma unroll
        for (int i = 0; i < 8; i++) {
            float4 t = *(const float4*)(sAssign + (n0 + i) * 128 + kk);
            a_[i][0] = t.x; a_[i][1] = t.y; a_[i][2] = t.z; a_[i][3] = t.w;
        }
#pragma unroll
        for (int q = 0; q < 4; q++) {
            unsigned long long w01 = pack2(w_[q][0], w_[q][1]);
            unsigned long long w23 = pack2(w_[q][2], w_[q][3]);
#pragma unroll
            for (int i = 0; i < 8; i++) {
                unsigned long long aa = pack2(a_[i][q], a_[i][q]);
                ffma2(o2[i][0], aa, w01);
                ffma2(o2[i][1], aa, w23);
            }
        }
    }

#pragma unroll
    for (int i = 0; i < 8; i++) {
        float2 v01 = unpack2(o2[i][0]);
        float2 v23 = unpack2(o2[i][1]);
        *(float4*)(out + (size_t)(node0 + n0 + i) * 128 + c0) =
            make_float4(v01.x, v01.y, v23.x, v23.y);
    }
}

// ---------------- launch (exactly 6 kernels; ncu -s 5 lands on k_fused) ----
extern "C" void kernel_launch(void* const* d_in, const int* in_sizes, int n_in,
                              void* d_out, int out_size) {
    (void)in_sizes; (void)n_in; (void)out_size;
    const float* h    = (const float*)d_in[0];
    const float* fea  = (const float*)d_in[1];
    const float* Ws   = (const float*)d_in[2];
    const float* Wn   = (const float*)d_in[3];
    const float* bias = (const float*)d_in[4];
    const void*  esrc = d_in[5];
    const void*  edst = d_in[6];
    float* out = (float*)d_out;

    cudaFuncSetAttribute(k_fused, cudaFuncAttributeMaxDynamicSharedMemorySize,
                         SMEM_BYTES);

    k_init <<<(NTOT + 1023) / 1024, 1024>>>((const int*)esrc, (const int*)edst);
    k_count<<<(EDGES + 255) / 256, 256>>>(edst);
    k_scan <<<1, 1024>>>();
    k_fill <<<(EDGES + 255) / 256, 256>>>(esrc, edst);
    k_agg  <<<(NTOT * 32) / 512, 512>>>(h);
    k_fused<<<NTOT / 64, 256, SMEM_BYTES>>>(h, fea, Ws, Wn, bias, out);
}

// round 9
// speedup vs baseline: 1.3316x; 1.3222x over previous
#include <cuda_runtime.h>

#define NTOT  65536
#define BGRAPH 64
#define NPG   1024
#define KC    128
#define DD    128
#define EDGES 1048576

// ---------------- scratch (device globals: allocation-free) ----------------
// g_deg starts zero (module load) and is RESTORED to zero by k_fill's
// countdown allocator every launch sequence -> no init kernel needed.
__device__ __align__(16) int g_deg[NTOT];
__device__ __align__(16) int g_off[NTOT + 4];
__device__ int g_adj[EDGES];

// ---------------- packed f32x2 helpers (Blackwell FFMA2 path) --------------
__device__ __forceinline__ unsigned long long pack2(float lo, float hi) {
    unsigned long long r;
    asm("mov.b64 %0, {%1, %2};" : "=l"(r) : "f"(lo), "f"(hi));
    return r;
}
__device__ __forceinline__ void ffma2(unsigned long long& d,
                                      unsigned long long a,
                                      unsigned long long b) {
    asm("fma.rn.f32x2 %0, %1, %2, %0;" : "+l"(d) : "l"(a), "l"(b));
}
__device__ __forceinline__ float2 unpack2(unsigned long long v) {
    float2 f;
    asm("mov.b64 {%0, %1}, %2;" : "=f"(f.x), "=f"(f.y) : "l"(v));
    return f;
}

// ---------------- edge dtype detect (per block, smem broadcast) ------------
// int64 ids < 2^31 -> every odd 32-bit word is 0; int32 -> random node ids.
__device__ __forceinline__ int detect_is64(const int* __restrict__ buf) {
    int az = 1;
#pragma unroll
    for (int k = 1; k <= 15; k += 2) az &= (buf[k] == 0);
    return az;
}
__device__ __forceinline__ int edge_id(const void* buf, int e, int is64) {
    return is64 ? (int)((const long long*)buf)[e] : ((const int*)buf)[e];
}

// ---------------- 1) degree count ----------------
__global__ void k_count(const void* __restrict__ dst) {
    __shared__ int s_is64;
    if (threadIdx.x == 0) s_is64 = detect_is64((const int*)dst);
    __syncthreads();
    int e = blockIdx.x * blockDim.x + threadIdx.x;
    if (e < EDGES) {
        int d = edge_id(dst, e, s_is64);
        if (d >= 0 && d < NTOT) atomicAdd(&g_deg[d], 1);
    }
}

// ---------------- 2) coalesced single-block exclusive scan -----------------
// 32 warps; warp w owns 2048 contiguous elements, read as int4 (coalesced).
__global__ void k_scan() {
    __shared__ int warp_tot[32];
    __shared__ int warp_pre[32];
    int t = threadIdx.x;
    int lane = t & 31, w = t >> 5;
    const int4* deg4 = (const int4*)g_deg;
    int base4 = w * 512;                    // 512 int4 = 2048 ints per warp

    // pass 1: warp totals
    int s = 0;
#pragma unroll
    for (int q = 0; q < 16; q++) {
        int4 v = deg4[base4 + q * 32 + lane];
        s += (v.x + v.y) + (v.z + v.w);
    }
#pragma unroll
    for (int o = 16; o > 0; o >>= 1) s += __shfl_xor_sync(0xffffffffu, s, o);
    if (lane == 0) warp_tot[w] = s;
    __syncthreads();

    if (w == 0) {
        int v = warp_tot[lane];
        int inc = v;
#pragma unroll
        for (int o = 1; o < 32; o <<= 1) {
            int u = __shfl_up_sync(0xffffffffu, inc, o);
            if (lane >= o) inc += u;
        }
        warp_pre[lane] = inc - v;
        if (lane == 31) g_off[NTOT] = inc;  // grand total
    }
    __syncthreads();

    // pass 2: per-128-chunk warp scan, int4 in / int4 out (coalesced)
    int run = warp_pre[w];
#pragma unroll
    for (int q = 0; q < 16; q++) {
        int4 v = deg4[base4 + q * 32 + lane];
        int ls = (v.x + v.y) + (v.z + v.w);
        int inc = ls;
#pragma unroll
        for (int o = 1; o < 32; o <<= 1) {
            int u = __shfl_up_sync(0xffffffffu, inc, o);
            if (lane >= o) inc += u;
        }
        int ex = run + inc - ls;
        int4 o4;
        o4.x = ex;
        o4.y = ex + v.x;
        o4.z = ex + v.x + v.y;
        o4.w = ex + v.x + v.y + v.z;
        ((int4*)g_off)[base4 + q * 32 + lane] = o4;
        run += __shfl_sync(0xffffffffu, inc, 31);
    }
}

// ---------------- 3) bucket fill (countdown: restores g_deg to 0) ----------
__global__ void k_fill(const void* __restrict__ src, const void* __restrict__ dst) {
    __shared__ int s_is64;
    if (threadIdx.x == 0) s_is64 = detect_is64((const int*)dst);
    __syncthreads();
    int e = blockIdx.x * blockDim.x + threadIdx.x;
    if (e < EDGES) {
        int d = edge_id(dst, e, s_is64);
        int s = edge_id(src, e, s_is64);
        if (d >= 0 && d < NTOT && s >= 0 && s < NTOT) {
            int pos = atomicAdd(&g_deg[d], -1) - 1;   // deg-1 .. 0
            g_adj[g_off[d] + pos] = s;
        }
    }
}

// ------- 4) fused: neigh-gather + GEMM1 + bias/relu/softmax + GEMM2 --------
// Tile: 64 nodes x 128 cols per block, 256 threads (8 warps x 8 nodes).
// smem: sA [64][256] (h | neigh-gathered-in-place) = 64KB
//       sW [256][128] (Ws ; Wn)                    = 128KB
//       sB [128]
// phase2 aliases: sAssign -> sA, sFea -> sW.
#define SMEM_FLOATS (64 * 256 + 256 * 128 + 128)
#define SMEM_BYTES  (SMEM_FLOATS * 4)

extern __shared__ float smem[];

__global__ void __launch_bounds__(256, 1)
k_fused(const float* __restrict__ h,
        const float* __restrict__ fea,
        const float* __restrict__ Ws,
        const float* __restrict__ Wn,
        const float* __restrict__ bias,
        float* __restrict__ out) {
    float* sA = smem;                    // 64*256
    float* sW = smem + 64 * 256;         // 256*128
    float* sB = sW + 256 * 128;          // 128

    const int tid = threadIdx.x;
    const int node0 = blockIdx.x * 64;
    const int lane = tid & 31, wrp = tid >> 5;
    const int n0 = wrp * 8;              // this warp's 8 nodes
    const int c0 = lane * 4;             // 4 cols per thread

    // ---- neighbor aggregation for this warp's 8 nodes -> sA[..][128..255] --
#pragma unroll 1
    for (int i = 0; i < 8; i++) {
        int node = node0 + n0 + i;
        int s = g_off[node], e = g_off[node + 1];
        float4 acc = make_float4(0.f, 0.f, 0.f, 0.f);
        int j = s;
        for (; j + 8 <= e; j += 8) {
            int idx[8];
#pragma unroll
            for (int q = 0; q < 8; q++) idx[q] = g_adj[j + q];
            float4 v[8];
#pragma unroll
            for (int q = 0; q < 8; q++)
                v[q] = __ldg((const float4*)(h + (size_t)idx[q] * 128) + lane);
#pragma unroll
            for (int q = 0; q < 8; q++) {
                acc.x += v[q].x; acc.y += v[q].y;
                acc.z += v[q].z; acc.w += v[q].w;
            }
        }
        for (; j < e; j++) {
            float4 v0 = __ldg((const float4*)(h + (size_t)g_adj[j] * 128) + lane);
            acc.x += v0.x; acc.y += v0.y; acc.z += v0.z; acc.w += v0.w;
        }
        float inv = 1.0f / fmaxf((float)(e - s), 1.0f);
        *(float4*)(sA + (n0 + i) * 256 + 128 + c0) =
            make_float4(acc.x * inv, acc.y * inv, acc.z * inv, acc.w * inv);
    }

    // ---- bulk copies: h -> sA[..][0..127], weights, bias ----
    for (int i = tid; i < 64 * 32; i += 256) {
        int r = i >> 5, c = (i & 31) << 2;
        *(float4*)(sA + r * 256 + c) =
            *(const float4*)(h + (size_t)(node0 + r) * 128 + c);
    }
    for (int i = tid; i < 128 * 32; i += 256) {
        int r = i >> 5, c = (i & 31) << 2;
        *(float4*)(sW + r * 128 + c)         = *(const float4*)(Ws + r * 128 + c);
        *(float4*)(sW + (128 + r) * 128 + c) = *(const float4*)(Wn + r * 128 + c);
    }
    if (tid < 128) sB[tid] = bias[tid];
    __syncthreads();

    unsigned long long acc2[8][2];
#pragma unroll
    for (int i = 0; i < 8; i++) { acc2[i][0] = 0ULL; acc2[i][1] = 0ULL; }

    // ---- GEMM1: logits = [h|neigh] @ [Ws;Wn]  (K=256) ----
    for (int kk = 0; kk < 256; kk += 4) {
        float w_[4][4];
#pragma unroll
        for (int q = 0; q < 4; q++) {
            float4 t = *(const float4*)(sW + (kk + q) * 128 + c0);
            w_[q][0] = t.x; w_[q][1] = t.y; w_[q][2] = t.z; w_[q][3] = t.w;
        }
        float a_[8][4];
#pragma unroll
        for (int i = 0; i < 8; i++) {
            float4 t = *(const float4*)(sA + (n0 + i) * 256 + kk);
            a_[i][0] = t.x; a_[i][1] = t.y; a_[i][2] = t.z; a_[i][3] = t.w;
        }
#pragma unroll
        for (int q = 0; q < 4; q++) {
            unsigned long long w01 = pack2(w_[q][0], w_[q][1]);
            unsigned long long w23 = pack2(w_[q][2], w_[q][3]);
#pragma unroll
            for (int i = 0; i < 8; i++) {
                unsigned long long aa = pack2(a_[i][q], a_[i][q]);
                ffma2(acc2[i][0], aa, w01);
                ffma2(acc2[i][1], aa, w23);
            }
        }
    }

    // ---- bias + relu + row softmax (row in one warp: 4 cols/lane) ----
    float4 b4 = *(const float4*)(sB + c0);
    float probs[8][4];
#pragma unroll
    for (int i = 0; i < 8; i++) {
        float2 v01 = unpack2(acc2[i][0]);
        float2 v23 = unpack2(acc2[i][1]);
        float x0 = fmaxf(v01.x + b4.x, 0.f);
        float x1 = fmaxf(v01.y + b4.y, 0.f);
        float x2 = fmaxf(v23.x + b4.z, 0.f);
        float x3 = fmaxf(v23.y + b4.w, 0.f);
        float m = fmaxf(fmaxf(x0, x1), fmaxf(x2, x3));
#pragma unroll
        for (int o = 16; o > 0; o >>= 1)
            m = fmaxf(m, __shfl_xor_sync(0xffffffffu, m, o));
        x0 = __expf(x0 - m); x1 = __expf(x1 - m);
        x2 = __expf(x2 - m); x3 = __expf(x3 - m);
        float ssum = (x0 + x1) + (x2 + x3);
#pragma unroll
        for (int o = 16; o > 0; o >>= 1)
            ssum += __shfl_xor_sync(0xffffffffu, ssum, o);
        float inv = 1.0f / ssum;
        probs[i][0] = x0 * inv; probs[i][1] = x1 * inv;
        probs[i][2] = x2 * inv; probs[i][3] = x3 * inv;
    }

    __syncthreads();   // done reading sA/sW before aliasing

    float* sAssign = sA;   // [64][128]
    float* sFea    = sW;   // [128][128]
#pragma unroll
    for (int i = 0; i < 8; i++) {
        *(float4*)(sAssign + (n0 + i) * 128 + c0) =
            make_float4(probs[i][0], probs[i][1], probs[i][2], probs[i][3]);
    }
    {   // per-graph fea slice (graph = node0 / 1024)
        const float* feaG = fea + (size_t)(node0 >> 10) * KC * DD;
        for (int i = tid; i < 128 * 32; i += 256) {
            int r = i >> 5, c = (i & 31) << 2;
            *(float4*)(sFea + r * 128 + c) = *(const float4*)(feaG + r * 128 + c);
        }
    }
    __syncthreads();

    // ---- GEMM2: out = assign @ fea_g  (K=128) ----
    unsigned long long o2[8][2];
#pragma unroll
    for (int i = 0; i < 8; i++) { o2[i][0] = 0ULL; o2[i][1] = 0ULL; }

    for (int kk = 0; kk < 128; kk += 4) {
        float w_[4][4];
#pragma unroll
        for (int q = 0; q < 4; q++) {
            float4 t = *(const float4*)(sFea + (kk + q) * 128 + c0);
            w_[q][0] = t.x; w_[q][1] = t.y; w_[q][2] = t.z; w_[q][3] = t.w;
        }
        float a_[8][4];
#pragma unroll
        for (int i = 0; i < 8; i++) {
            float4 t = *(const float4*)(sAssign + (n0 + i) * 128 + kk);
            a_[i][0] = t.x; a_[i][1] = t.y; a_[i][2] = t.z; a_[i][3] = t.w;
        }
#pragma unroll
        for (int q = 0; q < 4; q++) {
            unsigned long long w01 = pack2(w_[q][0], w_[q][1]);
            unsigned long long w23 = pack2(w_[q][2], w_[q][3]);
#pragma unroll
            for (int i = 0; i < 8; i++) {
                unsigned long long aa = pack2(a_[i][q], a_[i][q]);
                ffma2(o2[i][0], aa, w01);
                ffma2(o2[i][1], aa, w23);
            }
        }
    }

#pragma unroll
    for (int i = 0; i < 8; i++) {
        float2 v01 = unpack2(o2[i][0]);
        float2 v23 = unpack2(o2[i][1]);
        *(float4*)(out + (size_t)(node0 + n0 + i) * 128 + c0) =
            make_float4(v01.x, v01.y, v23.x, v23.y);
    }
}

// ---------------- launch (4 kernels; profiler lands on k_fused = #4) -------
extern "C" void kernel_launch(void* const* d_in, const int* in_sizes, int n_in,
                              void* d_out, int out_size) {
    (void)in_sizes; (void)n_in; (void)out_size;
    const float* h    = (const float*)d_in[0];
    const float* fea  = (const float*)d_in[1];
    const float* Ws   = (const float*)d_in[2];
    const float* Wn   = (const float*)d_in[3];
    const float* bias = (const float*)d_in[4];
    const void*  esrc = d_in[5];
    const void*  edst = d_in[6];
    float* out = (float*)d_out;

    cudaFuncSetAttribute(k_fused, cudaFuncAttributeMaxDynamicSharedMemorySize,
                         SMEM_BYTES);

    k_count<<<(EDGES + 255) / 256, 256>>>(edst);
    k_scan <<<1, 1024>>>();
    k_fill <<<(EDGES + 255) / 256, 256>>>(esrc, edst);
    k_fused<<<NTOT / 64, 256, SMEM_BYTES>>>(h, fea, Ws, Wn, bias, out);
}